// round 15
// baseline (speedup 1.0000x reference)
#include <cuda_runtime.h>
#include <stdint.h>
#include <float.h>

#define P_TOTAL 80000
#define OUTC    64
#define XL      432
#define YL      496
#define BS      4
#define PLANE   (YL * XL)            // 214272
#define K1_BLOCKS 740                // 5 blocks/SM x 148 SMs: one full-residency wave
#define K1_WARPS  (K1_BLOCKS * 8)    // 5920 warps -> 13.5 pillars per warp

// Scratch (device globals — no allocation allowed)
__device__ float g_pooled[P_TOTAL * OUTC];   // 20.5 MB, L2-resident
__device__ int   g_map[BS * YL * XL];        // inverse map, memset to -1

__device__ __forceinline__ uint64_t pack2s(float x) {
    uint64_t r; asm("mov.b64 %0, {%1,%1};" : "=l"(r) : "f"(x)); return r;
}
__device__ __forceinline__ uint64_t mul2(uint64_t a, uint64_t b) {
    uint64_t d;
    asm("mul.rn.f32x2 %0, %1, %2;" : "=l"(d) : "l"(a), "l"(b));
    return d;
}
__device__ __forceinline__ uint64_t fma2(uint64_t a, uint64_t b, uint64_t c) {
    uint64_t d;
    asm("fma.rn.f32x2 %0, %1, %2, %3;" : "=l"(d) : "l"(a), "l"(b), "l"(c));
    return d;
}
__device__ __forceinline__ float2 unpack2(uint64_t v) {
    float2 f; asm("mov.b64 {%0,%1}, %2;" : "=f"(f.x), "=f"(f.y) : "l"(v)); return f;
}

// ---------------------------------------------------------------------------
// k1: grid-stride, one warp per pillar per iteration (R8 structure).
//  * SoA smem staging; inner loop reads point-pairs via uniform-address
//    LDS.64 broadcasts and does 8 packed fma.rn.f32x2 per 2 points.
//  * pc (bias + mean/center terms) decoupled from the point loop:
//    fp max is monotone, so max_q(pc + s_q) == pc + max_q(s_q) bit-exactly;
//    the shfl-reduction + divide no longer gate the inner loop.
//  * 740 blocks = exactly one full-residency wave at 48 regs.
// ---------------------------------------------------------------------------
__global__ void __launch_bounds__(256) k1(
    const float4* __restrict__ pillars,
    const int*    __restrict__ npoints,
    const int4*   __restrict__ coors,
    const float*  __restrict__ conv_w,
    const float*  __restrict__ gamma,
    const float*  __restrict__ beta,
    const float*  __restrict__ mean,
    const float*  __restrict__ var)
{
    __shared__ float sW[10][OUTC];
    __shared__ float sf[8][4][32];   // [warp][feature][point]

    const int tid  = threadIdx.x;
    const int w    = tid >> 5;
    const int lane = tid & 31;

    if (tid < OUTC) {
        const int c = tid;
        const float a  = gamma[c] * rsqrtf(var[c] + 1e-3f);
        const float bb = beta[c] - mean[c] * a;
        float u[9];
#pragma unroll
        for (int k = 0; k < 9; k++) u[k] = conv_w[c * 9 + k] * a;
        sW[0][c] = u[0] + u[4] + u[7];
        sW[1][c] = u[1] + u[5] + u[8];
        sW[2][c] = u[2] + u[6];
        sW[3][c] = u[3];
        sW[4][c] = -u[4];
        sW[5][c] = -u[5];
        sW[6][c] = -u[6];
        sW[7][c] = -u[7];
        sW[8][c] = -u[8];
        sW[9][c] = bb;
    }
    __syncthreads();

    const int c0 = lane, c1 = lane + 32;
    const float w0a = sW[0][c0], w1a = sW[1][c0], w2a = sW[2][c0], w3a = sW[3][c0];
    const float w0b = sW[0][c1], w1b = sW[1][c1], w2b = sW[2][c1], w3b = sW[3][c1];
    const uint64_t W0a = pack2s(w0a), W1a = pack2s(w1a);
    const uint64_t W2a = pack2s(w2a), W3a = pack2s(w3a);
    const uint64_t W0b = pack2s(w0b), W1b = pack2s(w1b);
    const uint64_t W2b = pack2s(w2b), W3b = pack2s(w3b);
    const float n4a = sW[4][c0], n5a = sW[5][c0], n6a = sW[6][c0];
    const float n7a = sW[7][c0], n8a = sW[8][c0], bba = sW[9][c0];
    const float n4b = sW[4][c1], n5b = sW[5][c1], n6b = sW[6][c1];
    const float n7b = sW[7][c1], n8b = sW[8][c1], bbb = sW[9][c1];

    const int gw = (blockIdx.x * 256 + tid) >> 5;
    float* const sf0 = sf[w][0];
    float* const sf1 = sf[w][1];
    float* const sf2 = sf[w][2];
    float* const sf3 = sf[w][3];

    for (int p = gw; p < P_TOTAL; p += K1_WARPS) {
        const float4 pt = pillars[p * 32 + lane];
        const int    np = npoints[p];
        const int4   cb = coors[p];

        __syncwarp();                 // prior iteration's readers done
        sf0[lane] = pt.x;
        sf1[lane] = pt.y;
        sf2[lane] = pt.z;
        sf3[lane] = pt.w;
        __syncwarp();                 // staging visible

        // reduction starts here but is consumed only in the epilogue
        float sx = pt.x, sy = pt.y, sz = pt.z;
#pragma unroll
        for (int o = 16; o > 0; o >>= 1) {
            sx += __shfl_xor_sync(0xFFFFFFFFu, sx, o);
            sy += __shfl_xor_sync(0xFFFFFFFFu, sy, o);
            sz += __shfl_xor_sync(0xFFFFFFFFu, sz, o);
        }

        // inner loop: max of dot-products WITHOUT the pillar constant
        float m0 = -FLT_MAX, m1 = -FLT_MAX;
        const int npair = np >> 1;
#pragma unroll 2
        for (int q = 0; q < npair; q++) {
            const uint64_t f0 = *(const uint64_t*)(sf0 + 2 * q);
            const uint64_t f1 = *(const uint64_t*)(sf1 + 2 * q);
            const uint64_t f2 = *(const uint64_t*)(sf2 + 2 * q);
            const uint64_t f3 = *(const uint64_t*)(sf3 + 2 * q);
            uint64_t dA = mul2(f0, W0a);
            uint64_t dB = mul2(f0, W0b);
            dA = fma2(f1, W1a, dA);  dB = fma2(f1, W1b, dB);
            dA = fma2(f2, W2a, dA);  dB = fma2(f2, W2b, dB);
            dA = fma2(f3, W3a, dA);  dB = fma2(f3, W3b, dB);
            const float2 va = unpack2(dA);   // register renaming, no ALU op
            const float2 vb = unpack2(dB);
            m0 = fmaxf(m0, fmaxf(va.x, va.y));
            m1 = fmaxf(m1, fmaxf(vb.x, vb.y));
        }
        if (np & 1) {                 // scalar tail for odd np
            const int q = np - 1;
            const float f0 = sf0[q], f1 = sf1[q], f2 = sf2[q], f3 = sf3[q];
            float d0 = f0 * w0a, d1 = f0 * w0b;
            d0 = fmaf(f1, w1a, d0);  d1 = fmaf(f1, w1b, d1);
            d0 = fmaf(f2, w2a, d0);  d1 = fmaf(f2, w2b, d1);
            d0 = fmaf(f3, w3a, d0);  d1 = fmaf(f3, w3b, d1);
            m0 = fmaxf(m0, d0);
            m1 = fmaxf(m1, d1);
        }

        // epilogue: pillar constant, then shift the max (bit-exact vs fused)
        const float inv = __fdividef(1.0f, (float)np);
        const float mx = sx * inv, my = sy * inv, mz = sz * inv;
        const float cx = (float)cb.y * 0.16f + 0.08f;
        const float cy = (float)cb.z * 0.16f + (0.08f - 39.68f);
        float pc0 = bba, pc1 = bbb;
        pc0 = fmaf(n4a, mx, pc0);  pc1 = fmaf(n4b, mx, pc1);
        pc0 = fmaf(n5a, my, pc0);  pc1 = fmaf(n5b, my, pc1);
        pc0 = fmaf(n6a, mz, pc0);  pc1 = fmaf(n6b, mz, pc1);
        pc0 = fmaf(n7a, cx, pc0);  pc1 = fmaf(n7b, cx, pc1);
        pc0 = fmaf(n8a, cy, pc0);  pc1 = fmaf(n8b, cy, pc1);

        m0 += pc0;
        m1 += pc1;
        if (np < 32) { m0 = fmaxf(m0, bba); m1 = fmaxf(m1, bbb); }  // masked pts => bias
        m0 = fmaxf(m0, 0.0f);
        m1 = fmaxf(m1, 0.0f);

        g_pooled[p * OUTC + c0] = m0;                 // coalesced
        g_pooled[p * OUTC + c1] = m1;
        if (lane == 0)
            g_map[(cb.x * YL + cb.z) * XL + cb.y] = p;
    }
}

// ---------------------------------------------------------------------------
// k2 (R8 version — measured at the ~4.5 TB/s write-turnaround ceiling across
// three structurally different implementations; its interior is done):
// block = 4 output rows (blockDim 108x4); each thread owns 4 consecutive x.
// int4 map read, LDG.128 gathers from L2-resident g_pooled (~9% cells
// non-empty), register transpose, one streaming STG.128 per channel row.
// Empty cells emit zeros — replaces the 219 MB memset.
// ---------------------------------------------------------------------------
__global__ void __launch_bounds__(448) k2(float* __restrict__ out)
{
    const int chunk = threadIdx.x;                    // 0..107
    const int row   = blockIdx.x * 4 + threadIdx.y;   // 0..1983
    const int b = row / YL;
    const int y = row - b * YL;

    const int4 pid = *(const int4*)(g_map + row * XL + chunk * 4);

    const float4* s0 = (const float4*)(g_pooled + (pid.x < 0 ? 0 : pid.x) * OUTC);
    const float4* s1 = (const float4*)(g_pooled + (pid.y < 0 ? 0 : pid.y) * OUTC);
    const float4* s2 = (const float4*)(g_pooled + (pid.z < 0 ? 0 : pid.z) * OUTC);
    const float4* s3 = (const float4*)(g_pooled + (pid.w < 0 ? 0 : pid.w) * OUTC);

    float* op = out + ((size_t)b * OUTC * YL + y) * XL + chunk * 4;  // c=0 plane

    const float4 z4 = make_float4(0.f, 0.f, 0.f, 0.f);
#pragma unroll
    for (int cg = 0; cg < 16; cg++) {
        const float4 v0 = (pid.x >= 0) ? __ldg(s0 + cg) : z4;
        const float4 v1 = (pid.y >= 0) ? __ldg(s1 + cg) : z4;
        const float4 v2 = (pid.z >= 0) ? __ldg(s2 + cg) : z4;
        const float4 v3 = (pid.w >= 0) ? __ldg(s3 + cg) : z4;
        __stcs((float4*)(op + (size_t)(4 * cg + 0) * PLANE),
               make_float4(v0.x, v1.x, v2.x, v3.x));
        __stcs((float4*)(op + (size_t)(4 * cg + 1) * PLANE),
               make_float4(v0.y, v1.y, v2.y, v3.y));
        __stcs((float4*)(op + (size_t)(4 * cg + 2) * PLANE),
               make_float4(v0.z, v1.z, v2.z, v3.z));
        __stcs((float4*)(op + (size_t)(4 * cg + 3) * PLANE),
               make_float4(v0.w, v1.w, v2.w, v3.w));
    }
}

extern "C" void kernel_launch(void* const* d_in, const int* in_sizes, int n_in,
                              void* d_out, int out_size) {
    const float4* pillars  = (const float4*)d_in[0];
    const int*    npoints  = (const int*)d_in[1];
    const int4*   coors    = (const int4*)d_in[2];
    const float*  conv_w   = (const float*)d_in[3];
    const float*  bn_gamma = (const float*)d_in[4];
    const float*  bn_beta  = (const float*)d_in[5];
    const float*  bn_mean  = (const float*)d_in[6];
    const float*  bn_var   = (const float*)d_in[7];
    float* out = (float*)d_out;

    void* map_ptr = nullptr;
    cudaGetSymbolAddress(&map_ptr, g_map);
    cudaMemsetAsync(map_ptr, 0xFF, sizeof(int) * BS * YL * XL);   // map = -1

    k1<<<K1_BLOCKS, 256>>>(pillars, npoints, coors, conv_w,
                           bn_gamma, bn_beta, bn_mean, bn_var);
    dim3 blk2(108, 4);
    k2<<<(BS * YL) / 4, blk2>>>(out);
}

// round 17
// speedup vs baseline: 1.0616x; 1.0616x over previous
#include <cuda_runtime.h>
#include <stdint.h>
#include <float.h>

#define P_TOTAL 80000
#define OUTC    64
#define XL      432
#define YL      496
#define BS      4
#define PLANE   (YL * XL)            // 214272
#define K1_BLOCKS 1480               // 2 perfectly balanced waves at 5 blocks/SM
#define K1_WARPS  (K1_BLOCKS * 8)    // 11840 warps -> 6.76 pillars per warp

// Scratch (device globals — no allocation allowed)
__device__ float g_pooled[P_TOTAL * OUTC];   // 20.5 MB, L2-resident
__device__ int   g_map[BS * YL * XL];        // inverse map, memset to -1

__device__ __forceinline__ uint64_t pack2s(float x) {
    uint64_t r; asm("mov.b64 %0, {%1,%1};" : "=l"(r) : "f"(x)); return r;
}
__device__ __forceinline__ uint64_t fma2(uint64_t a, uint64_t b, uint64_t c) {
    uint64_t d;
    asm("fma.rn.f32x2 %0, %1, %2, %3;" : "=l"(d) : "l"(a), "l"(b), "l"(c));
    return d;
}
__device__ __forceinline__ float2 unpack2(uint64_t v) {
    float2 f; asm("mov.b64 {%0,%1}, %2;" : "=f"(f.x), "=f"(f.y) : "l"(v)); return f;
}

// ---------------------------------------------------------------------------
// k1: grid-stride, one warp per pillar per iteration (exact R8 dataflow —
// the empirically fastest variant). Only change vs R8: grid 1184 -> 1480
// (two perfectly balanced full-residency waves at 5 blocks/SM, no ragged tail).
//  * SoA smem staging; inner loop reads point-pairs via uniform-address
//    LDS.64 broadcasts and does 8 packed fma.rn.f32x2 per 2 points with the
//    pillar constant folded into the accumulator init.
// ---------------------------------------------------------------------------
__global__ void __launch_bounds__(256) k1(
    const float4* __restrict__ pillars,
    const int*    __restrict__ npoints,
    const int4*   __restrict__ coors,
    const float*  __restrict__ conv_w,
    const float*  __restrict__ gamma,
    const float*  __restrict__ beta,
    const float*  __restrict__ mean,
    const float*  __restrict__ var)
{
    __shared__ float sW[10][OUTC];
    __shared__ float sf[8][4][32];   // [warp][feature][point]

    const int tid  = threadIdx.x;
    const int w    = tid >> 5;
    const int lane = tid & 31;

    if (tid < OUTC) {
        const int c = tid;
        const float a  = gamma[c] * rsqrtf(var[c] + 1e-3f);
        const float bb = beta[c] - mean[c] * a;
        float u[9];
#pragma unroll
        for (int k = 0; k < 9; k++) u[k] = conv_w[c * 9 + k] * a;
        sW[0][c] = u[0] + u[4] + u[7];
        sW[1][c] = u[1] + u[5] + u[8];
        sW[2][c] = u[2] + u[6];
        sW[3][c] = u[3];
        sW[4][c] = -u[4];
        sW[5][c] = -u[5];
        sW[6][c] = -u[6];
        sW[7][c] = -u[7];
        sW[8][c] = -u[8];
        sW[9][c] = bb;
    }
    __syncthreads();

    const int c0 = lane, c1 = lane + 32;
    const float w0a = sW[0][c0], w1a = sW[1][c0], w2a = sW[2][c0], w3a = sW[3][c0];
    const float w0b = sW[0][c1], w1b = sW[1][c1], w2b = sW[2][c1], w3b = sW[3][c1];
    const uint64_t W0a = pack2s(w0a), W1a = pack2s(w1a);
    const uint64_t W2a = pack2s(w2a), W3a = pack2s(w3a);
    const uint64_t W0b = pack2s(w0b), W1b = pack2s(w1b);
    const uint64_t W2b = pack2s(w2b), W3b = pack2s(w3b);
    const float n4a = sW[4][c0], n5a = sW[5][c0], n6a = sW[6][c0];
    const float n7a = sW[7][c0], n8a = sW[8][c0], bba = sW[9][c0];
    const float n4b = sW[4][c1], n5b = sW[5][c1], n6b = sW[6][c1];
    const float n7b = sW[7][c1], n8b = sW[8][c1], bbb = sW[9][c1];

    const int gw = (blockIdx.x * 256 + tid) >> 5;
    float* const sf0 = sf[w][0];
    float* const sf1 = sf[w][1];
    float* const sf2 = sf[w][2];
    float* const sf3 = sf[w][3];

    for (int p = gw; p < P_TOTAL; p += K1_WARPS) {
        const float4 pt = pillars[p * 32 + lane];
        const int    np = npoints[p];
        const int4   cb = coors[p];

        __syncwarp();                 // prior iteration's readers done
        sf0[lane] = pt.x;
        sf1[lane] = pt.y;
        sf2[lane] = pt.z;
        sf3[lane] = pt.w;
        __syncwarp();                 // staging visible

        // warp-wide sums over ALL 32 points (reference sums the full axis)
        float sx = pt.x, sy = pt.y, sz = pt.z;
#pragma unroll
        for (int o = 16; o > 0; o >>= 1) {
            sx += __shfl_xor_sync(0xFFFFFFFFu, sx, o);
            sy += __shfl_xor_sync(0xFFFFFFFFu, sy, o);
            sz += __shfl_xor_sync(0xFFFFFFFFu, sz, o);
        }

        const float inv = __fdividef(1.0f, (float)np);
        const float mx = sx * inv, my = sy * inv, mz = sz * inv;
        const float cx = (float)cb.y * 0.16f + 0.08f;
        const float cy = (float)cb.z * 0.16f + (0.08f - 39.68f);

        float pc0 = bba, pc1 = bbb;
        pc0 = fmaf(n4a, mx, pc0);  pc1 = fmaf(n4b, mx, pc1);
        pc0 = fmaf(n5a, my, pc0);  pc1 = fmaf(n5b, my, pc1);
        pc0 = fmaf(n6a, mz, pc0);  pc1 = fmaf(n6b, mz, pc1);
        pc0 = fmaf(n7a, cx, pc0);  pc1 = fmaf(n7b, cx, pc1);
        pc0 = fmaf(n8a, cy, pc0);  pc1 = fmaf(n8b, cy, pc1);
        const uint64_t pcA = pack2s(pc0);
        const uint64_t pcB = pack2s(pc1);

        float m0 = -FLT_MAX, m1 = -FLT_MAX;
        const int npair = np >> 1;
#pragma unroll 2
        for (int q = 0; q < npair; q++) {
            const uint64_t f0 = *(const uint64_t*)(sf0 + 2 * q);
            const uint64_t f1 = *(const uint64_t*)(sf1 + 2 * q);
            const uint64_t f2 = *(const uint64_t*)(sf2 + 2 * q);
            const uint64_t f3 = *(const uint64_t*)(sf3 + 2 * q);
            uint64_t dA = pcA, dB = pcB;
            dA = fma2(f0, W0a, dA);  dB = fma2(f0, W0b, dB);
            dA = fma2(f1, W1a, dA);  dB = fma2(f1, W1b, dB);
            dA = fma2(f2, W2a, dA);  dB = fma2(f2, W2b, dB);
            dA = fma2(f3, W3a, dA);  dB = fma2(f3, W3b, dB);
            const float2 va = unpack2(dA);   // register renaming, no ALU op
            const float2 vb = unpack2(dB);
            m0 = fmaxf(m0, fmaxf(va.x, va.y));
            m1 = fmaxf(m1, fmaxf(vb.x, vb.y));
        }
        if (np & 1) {                 // scalar tail for odd np
            const int q = np - 1;
            const float f0 = sf0[q], f1 = sf1[q], f2 = sf2[q], f3 = sf3[q];
            float d0 = pc0, d1 = pc1;
            d0 = fmaf(f0, w0a, d0);  d1 = fmaf(f0, w0b, d1);
            d0 = fmaf(f1, w1a, d0);  d1 = fmaf(f1, w1b, d1);
            d0 = fmaf(f2, w2a, d0);  d1 = fmaf(f2, w2b, d1);
            d0 = fmaf(f3, w3a, d0);  d1 = fmaf(f3, w3b, d1);
            m0 = fmaxf(m0, d0);
            m1 = fmaxf(m1, d1);
        }
        if (np < 32) { m0 = fmaxf(m0, bba); m1 = fmaxf(m1, bbb); }  // masked pts => bias
        m0 = fmaxf(m0, 0.0f);
        m1 = fmaxf(m1, 0.0f);

        g_pooled[p * OUTC + c0] = m0;                 // coalesced
        g_pooled[p * OUTC + c1] = m1;
        if (lane == 0)
            g_map[(cb.x * YL + cb.z) * XL + cb.y] = p;
    }
}

// ---------------------------------------------------------------------------
// k2 (R8 version — pinned at the ~4.5 TB/s write-turnaround ceiling across
// three structurally different implementations; its interior is done):
// block = 4 output rows (blockDim 108x4); each thread owns 4 consecutive x.
// int4 map read, LDG.128 gathers from L2-resident g_pooled (~9% cells
// non-empty), register transpose, one streaming STG.128 per channel row.
// Empty cells emit zeros — replaces the 219 MB memset.
// ---------------------------------------------------------------------------
__global__ void __launch_bounds__(448) k2(float* __restrict__ out)
{
    const int chunk = threadIdx.x;                    // 0..107
    const int row   = blockIdx.x * 4 + threadIdx.y;   // 0..1983
    const int b = row / YL;
    const int y = row - b * YL;

    const int4 pid = *(const int4*)(g_map + row * XL + chunk * 4);

    const float4* s0 = (const float4*)(g_pooled + (pid.x < 0 ? 0 : pid.x) * OUTC);
    const float4* s1 = (const float4*)(g_pooled + (pid.y < 0 ? 0 : pid.y) * OUTC);
    const float4* s2 = (const float4*)(g_pooled + (pid.z < 0 ? 0 : pid.z) * OUTC);
    const float4* s3 = (const float4*)(g_pooled + (pid.w < 0 ? 0 : pid.w) * OUTC);

    float* op = out + ((size_t)b * OUTC * YL + y) * XL + chunk * 4;  // c=0 plane

    const float4 z4 = make_float4(0.f, 0.f, 0.f, 0.f);
#pragma unroll
    for (int cg = 0; cg < 16; cg++) {
        const float4 v0 = (pid.x >= 0) ? __ldg(s0 + cg) : z4;
        const float4 v1 = (pid.y >= 0) ? __ldg(s1 + cg) : z4;
        const float4 v2 = (pid.z >= 0) ? __ldg(s2 + cg) : z4;
        const float4 v3 = (pid.w >= 0) ? __ldg(s3 + cg) : z4;
        __stcs((float4*)(op + (size_t)(4 * cg + 0) * PLANE),
               make_float4(v0.x, v1.x, v2.x, v3.x));
        __stcs((float4*)(op + (size_t)(4 * cg + 1) * PLANE),
               make_float4(v0.y, v1.y, v2.y, v3.y));
        __stcs((float4*)(op + (size_t)(4 * cg + 2) * PLANE),
               make_float4(v0.z, v1.z, v2.z, v3.z));
        __stcs((float4*)(op + (size_t)(4 * cg + 3) * PLANE),
               make_float4(v0.w, v1.w, v2.w, v3.w));
    }
}

extern "C" void kernel_launch(void* const* d_in, const int* in_sizes, int n_in,
                              void* d_out, int out_size) {
    const float4* pillars  = (const float4*)d_in[0];
    const int*    npoints  = (const int*)d_in[1];
    const int4*   coors    = (const int4*)d_in[2];
    const float*  conv_w   = (const float*)d_in[3];
    const float*  bn_gamma = (const float*)d_in[4];
    const float*  bn_beta  = (const float*)d_in[5];
    const float*  bn_mean  = (const float*)d_in[6];
    const float*  bn_var   = (const float*)d_in[7];
    float* out = (float*)d_out;

    void* map_ptr = nullptr;
    cudaGetSymbolAddress(&map_ptr, g_map);
    cudaMemsetAsync(map_ptr, 0xFF, sizeof(int) * BS * YL * XL);   // map = -1

    k1<<<K1_BLOCKS, 256>>>(pillars, npoints, coors, conv_w,
                           bn_gamma, bn_beta, bn_mean, bn_var);
    dim3 blk2(108, 4);
    k2<<<(BS * YL) / 4, blk2>>>(out);
}